// round 2
// baseline (speedup 1.0000x reference)
#include <cuda_runtime.h>
#include <cuda_fp16.h>
#include <cstdint>

// ---------------------------------------------------------------------------
// BayesKerasDense TT-dense: y = relu(x @ M + b)
//   M is the materialized TT-matrix from cores:
//   M[a,b] = sum_{r1,r2,r3} c0[0,a0,b0,r1] c1[r1,a1,b1,r2] c2[r2,a2,b2,r3] c3[r3,a3,b3,0]
//   a = (a0,a1,a2,a3) row-major, b = (b0,b1,b2,b3) row-major (verified vs. ref einsum).
// Pipeline: T2 = c0*c1 -> T3 = T2*c2 -> M(fp16, stored transposed) -> x->fp16
//           -> fp16 tensor-core GEMM (fp32 accum) + bias + relu.
// ---------------------------------------------------------------------------

#define NF 4096

// Scratch (device globals: allocation-free per harness rules)
__device__ float  g_T2[64 * 64 * 16];          // 256 KB
__device__ float  g_T3[512 * 512 * 16];        // 16.8 MB
__device__ __half g_Mt[(size_t)NF * NF];       // 32 MB, layout [b][a] (N x K row-major)
__device__ __half g_Xh[(size_t)NF * NF];       // 32 MB, layout [z][a] (M x K row-major)

// ---------------- stage 1: TT core contractions ----------------------------

__global__ void k_build_T2(const float* __restrict__ c0, const float* __restrict__ c1) {
    int idx = blockIdx.x * blockDim.x + threadIdx.x;     // 64*64*16 = 65536
    if (idx >= 64 * 64 * 16) return;
    int r2 = idx & 15;
    int q2 = (idx >> 4) & 63;
    int p2 = idx >> 10;
    int a0 = p2 >> 3, a1 = p2 & 7;
    int b0 = q2 >> 3, b1 = q2 & 7;
    float s = 0.f;
#pragma unroll
    for (int r1 = 0; r1 < 16; ++r1)
        s += c0[(a0 * 8 + b0) * 16 + r1] * c1[((r1 * 8 + a1) * 8 + b1) * 16 + r2];
    g_T2[idx] = s;
}

__global__ void k_build_T3(const float* __restrict__ c2) {
    int idx = blockIdx.x * blockDim.x + threadIdx.x;     // 512*512*16 = 4194304
    if (idx >= 512 * 512 * 16) return;
    int r3 = idx & 15;
    int q3 = (idx >> 4) & 511;
    int p3 = idx >> 13;
    int p2 = p3 >> 3, a2 = p3 & 7;
    int q2 = q3 >> 3, b2 = q3 & 7;
    const float* t2 = &g_T2[((p2 << 6) + q2) << 4];
    float s = 0.f;
#pragma unroll
    for (int r2 = 0; r2 < 16; ++r2)
        s += t2[r2] * c2[((r2 * 8 + a2) * 8 + b2) * 16 + r3];
    g_T3[idx] = s;
}

__global__ void k_build_M(const float* __restrict__ c3) {
    int idx = blockIdx.x * blockDim.x + threadIdx.x;     // 4096*4096 = 16777216
    if (idx >= NF * NF) return;
    int a = idx & (NF - 1);
    int b = idx >> 12;
    int a3 = a & 7, p3 = a >> 3;
    int b3 = b & 7, q3 = b >> 3;
    const float* t3 = &g_T3[(((size_t)p3 << 9) + q3) << 4];
    float s = 0.f;
#pragma unroll
    for (int r3 = 0; r3 < 16; ++r3)
        s += t3[r3] * c3[(r3 * 8 + a3) * 8 + b3];
    g_Mt[(size_t)b * NF + a] = __float2half(s);          // transposed store: [n][k]
}

__global__ void k_conv_x(const float4* __restrict__ x4) {
    int idx = blockIdx.x * blockDim.x + threadIdx.x;     // 4096*4096/4 = 4194304
    if (idx >= NF * NF / 4) return;
    float4 v = x4[idx];
    __half2* o = (__half2*)g_Xh;
    o[idx * 2 + 0] = __floats2half2_rn(v.x, v.y);
    o[idx * 2 + 1] = __floats2half2_rn(v.z, v.w);
}

// ---------------- stage 2: fp16 tensor-core GEMM ---------------------------
// C[4096 x 4096] = Xh[4096 x 4096] * Mt^T, fp32 accum, epilogue relu(+bias).

#define BM 128
#define BN 128
#define BK 32
#define LDS 40   // row stride in halves (32 data + 8 pad) -> 80B, conflict-free ldmatrix

__device__ __forceinline__ void cp_async16(void* smem, const void* gmem) {
    uint32_t s = (uint32_t)__cvta_generic_to_shared(smem);
    asm volatile("cp.async.cg.shared.global [%0], [%1], 16;\n" :: "r"(s), "l"(gmem));
}
__device__ __forceinline__ void cp_commit() { asm volatile("cp.async.commit_group;\n" ::: "memory"); }
__device__ __forceinline__ void cp_wait_all() { asm volatile("cp.async.wait_group 0;\n" ::: "memory"); }

__device__ __forceinline__ void ldmatrix_x4(uint32_t* r, const void* p) {
    uint32_t s = (uint32_t)__cvta_generic_to_shared(p);
    asm volatile("ldmatrix.sync.aligned.m8n8.x4.shared.b16 {%0,%1,%2,%3}, [%4];\n"
                 : "=r"(r[0]), "=r"(r[1]), "=r"(r[2]), "=r"(r[3]) : "r"(s));
}
__device__ __forceinline__ void ldmatrix_x2(uint32_t* r, const void* p) {
    uint32_t s = (uint32_t)__cvta_generic_to_shared(p);
    asm volatile("ldmatrix.sync.aligned.m8n8.x2.shared.b16 {%0,%1}, [%2];\n"
                 : "=r"(r[0]), "=r"(r[1]) : "r"(s));
}
__device__ __forceinline__ void mma16816(float* d, const uint32_t* a, const uint32_t* b) {
    asm volatile("mma.sync.aligned.m16n8k16.row.col.f32.f16.f16.f32 "
                 "{%0,%1,%2,%3}, {%4,%5,%6,%7}, {%8,%9}, {%0,%1,%2,%3};\n"
                 : "+f"(d[0]), "+f"(d[1]), "+f"(d[2]), "+f"(d[3])
                 : "r"(a[0]), "r"(a[1]), "r"(a[2]), "r"(a[3]), "r"(b[0]), "r"(b[1]));
}

__global__ __launch_bounds__(256, 2) void k_gemm(const float* __restrict__ bias,
                                                 float* __restrict__ out) {
    __shared__ __half As[2][BM * LDS];
    __shared__ __half Bs[2][BN * LDS];

    const int tid  = threadIdx.x;
    const int lane = tid & 31;
    const int warp = tid >> 5;
    const int warpM = warp >> 2;   // 0..1 -> 64-row slab
    const int warpN = warp & 3;    // 0..3 -> 32-col slab
    const int bm = blockIdx.y * BM;
    const int bn = blockIdx.x * BN;

    const __half* Ag = g_Xh;  // [z][k]
    const __half* Bg = g_Mt;  // [n][k]

    float acc[4][4][4];
#pragma unroll
    for (int i = 0; i < 4; i++)
#pragma unroll
        for (int j = 0; j < 4; j++)
#pragma unroll
            for (int k = 0; k < 4; k++) acc[i][j][k] = 0.f;

    // tile loader: 128 rows x 32 halves = 512 x 16B chunks per matrix; 2 chunks/thread
    auto load_tile = [&](int buf, int kk) {
#pragma unroll
        for (int i = 0; i < 2; ++i) {
            int cid = tid + i * 256;              // 0..511
            int r = cid >> 2, c = cid & 3;        // row, 16B chunk
            cp_async16(&As[buf][r * LDS + c * 8],
                       Ag + (size_t)(bm + r) * NF + kk + c * 8);
            cp_async16(&Bs[buf][r * LDS + c * 8],
                       Bg + (size_t)(bn + r) * NF + kk + c * 8);
        }
    };

    load_tile(0, 0);
    cp_commit();

    const int KT = NF / BK;  // 128
    for (int kt = 0; kt < KT; ++kt) {
        const int buf = kt & 1;
        cp_wait_all();
        __syncthreads();                 // smem buf ready; prev compute done before reuse
        if (kt + 1 < KT) {
            load_tile(buf ^ 1, (kt + 1) * BK);
            cp_commit();
        }
#pragma unroll
        for (int ks = 0; ks < 2; ++ks) {
            uint32_t af[4][4];
#pragma unroll
            for (int mi = 0; mi < 4; ++mi) {
                const __half* p = &As[buf][(warpM * 64 + mi * 16 + (lane & 15)) * LDS
                                           + ks * 16 + (lane >> 4) * 8];
                ldmatrix_x4(af[mi], p);
            }
            uint32_t bf[4][2];
#pragma unroll
            for (int ni = 0; ni < 4; ++ni) {
                const __half* p = &Bs[buf][(warpN * 32 + ni * 8 + (lane & 7)) * LDS
                                           + ks * 16 + ((lane >> 3) & 1) * 8];
                ldmatrix_x2(bf[ni], p);
            }
#pragma unroll
            for (int mi = 0; mi < 4; ++mi)
#pragma unroll
                for (int ni = 0; ni < 4; ++ni)
                    mma16816(acc[mi][ni], af[mi], bf[ni]);
        }
        __syncthreads();
    }

    // epilogue: relu(acc + bias), fp32 out
#pragma unroll
    for (int mi = 0; mi < 4; ++mi) {
#pragma unroll
        for (int ni = 0; ni < 4; ++ni) {
            int row = bm + warpM * 64 + mi * 16 + (lane >> 2);
            int col = bn + warpN * 32 + ni * 8 + (lane & 3) * 2;
            float b0 = bias[col], b1 = bias[col + 1];
            float* o0 = out + (size_t)row * NF + col;
            o0[0] = fmaxf(acc[mi][ni][0] + b0, 0.f);
            o0[1] = fmaxf(acc[mi][ni][1] + b1, 0.f);
            float* o1 = out + (size_t)(row + 8) * NF + col;
            o1[0] = fmaxf(acc[mi][ni][2] + b0, 0.f);
            o1[1] = fmaxf(acc[mi][ni][3] + b1, 0.f);
        }
    }
}

// ---------------------------------------------------------------------------

extern "C" void kernel_launch(void* const* d_in, const int* in_sizes, int n_in,
                              void* d_out, int out_size) {
    const float* x  = (const float*)d_in[0];  // [4096, 4096]
    const float* c0 = (const float*)d_in[1];  // (1,8,8,16)
    const float* c1 = (const float*)d_in[2];  // (16,8,8,16)
    const float* c2 = (const float*)d_in[3];  // (16,8,8,16)
    const float* c3 = (const float*)d_in[4];  // (16,8,8,1)
    const float* bv = (const float*)d_in[5];  // (4096,)
    float* out = (float*)d_out;

    k_build_T2<<<256, 256>>>(c0, c1);
    k_build_T3<<<16384, 256>>>(c2);
    k_build_M<<<65536, 256>>>(c3);
    k_conv_x<<<16384, 256>>>((const float4*)x);

    dim3 grid(NF / BN, NF / BM);  // (32, 32)
    k_gemm<<<grid, 256>>>(bv, out);
}

// round 5
// speedup vs baseline: 1.1853x; 1.1853x over previous
#include <cuda_runtime.h>
#include <cuda_fp16.h>
#include <cstdint>

// ---------------------------------------------------------------------------
// BayesKerasDense TT-dense: y = relu(x @ M + b)
// Stage 1: materialize TT-matrix M (fp16, transposed) + x -> fp16.
// Stage 2: mma.sync (HMMA) fp16 GEMM, fp32 accum (tcgen05/TMA rejected by the
//          toolchain's plain sm_103 PTX target).
// GEMM: CTA tile 128x256, BK=64, 4-stage cp.async ring (wait_group 2),
//       8 warps x (64x64), SW128-swizzled smem. Per-k-slice offset applied by
//       XOR (sw128(x + ks*32) == sw128(x) ^ (ks*32) when x bits5-6 are clear);
//       round 4 used ADD which carried past the smem end -> illegal access.
// ---------------------------------------------------------------------------

#define NF 4096

__device__ float  g_T2[64 * 64 * 16];          // 256 KB
__device__ float  g_T3[512 * 512 * 16];        // 16.8 MB
__device__ __half g_Mt[(size_t)NF * NF];       // 32 MB, [n][k]
__device__ __half g_Xh[(size_t)NF * NF];       // 32 MB, [m][k]

// ---------------- stage 1: TT core contractions ----------------------------

__global__ void k_build_T2(const float* __restrict__ c0, const float* __restrict__ c1) {
    int idx = blockIdx.x * blockDim.x + threadIdx.x;
    if (idx >= 64 * 64 * 16) return;
    int r2 = idx & 15;
    int q2 = (idx >> 4) & 63;
    int p2 = idx >> 10;
    int a0 = p2 >> 3, a1 = p2 & 7;
    int b0 = q2 >> 3, b1 = q2 & 7;
    float s = 0.f;
#pragma unroll
    for (int r1 = 0; r1 < 16; ++r1)
        s += c0[(a0 * 8 + b0) * 16 + r1] * c1[((r1 * 8 + a1) * 8 + b1) * 16 + r2];
    g_T2[idx] = s;
}

__global__ void k_build_T3(const float* __restrict__ c2) {
    int idx = blockIdx.x * blockDim.x + threadIdx.x;
    if (idx >= 512 * 512 * 16) return;
    int r3 = idx & 15;
    int q3 = (idx >> 4) & 511;
    int p3 = idx >> 13;
    int p2 = p3 >> 3, a2 = p3 & 7;
    int q2 = q3 >> 3, b2 = q3 & 7;
    const float* t2 = &g_T2[((p2 << 6) + q2) << 4];
    float s = 0.f;
#pragma unroll
    for (int r2 = 0; r2 < 16; ++r2)
        s += t2[r2] * c2[((r2 * 8 + a2) * 8 + b2) * 16 + r3];
    g_T3[idx] = s;
}

__global__ void k_build_M(const float* __restrict__ c3) {
    int idx = blockIdx.x * blockDim.x + threadIdx.x;
    if (idx >= NF * NF) return;
    int a = idx & (NF - 1);
    int b = idx >> 12;
    int a3 = a & 7, p3 = a >> 3;
    int b3 = b & 7, q3 = b >> 3;
    const float* t3 = &g_T3[(((size_t)p3 << 9) + q3) << 4];
    float s = 0.f;
#pragma unroll
    for (int r3 = 0; r3 < 16; ++r3)
        s += t3[r3] * c3[(r3 * 8 + a3) * 8 + b3];
    g_Mt[(size_t)b * NF + a] = __float2half(s);
}

__global__ void k_conv_x(const float4* __restrict__ x4) {
    int idx = blockIdx.x * blockDim.x + threadIdx.x;
    if (idx >= NF * NF / 4) return;
    float4 v = x4[idx];
    __half2* o = (__half2*)g_Xh;
    o[idx * 2 + 0] = __floats2half2_rn(v.x, v.y);
    o[idx * 2 + 1] = __floats2half2_rn(v.z, v.w);
}

// ---------------- stage 2: fp16 HMMA GEMM ----------------------------------

#define BM 128
#define BN 256
#define BK 64
#define KT (NF / BK)                 // 64
#define A_BYTES (BM * 128)           // 16 KB
#define B_BYTES (BN * 128)           // 32 KB
#define STAGE_BYTES (A_BYTES + B_BYTES)   // 48 KB
#define STAGES 4
#define SMEM_TOTAL (STAGES * STAGE_BYTES) // 192 KB

__device__ __forceinline__ uint32_t sw128(uint32_t off) {
    return off ^ ((off >> 3) & 0x70);
}
__device__ __forceinline__ void cp_async16(uint32_t smem, const void* gmem) {
    asm volatile("cp.async.cg.shared.global [%0], [%1], 16;\n" :: "r"(smem), "l"(gmem));
}
__device__ __forceinline__ void cp_commit() {
    asm volatile("cp.async.commit_group;\n" ::: "memory");
}
__device__ __forceinline__ void ldmatrix_x4(uint32_t* r, uint32_t s) {
    asm volatile("ldmatrix.sync.aligned.m8n8.x4.shared.b16 {%0,%1,%2,%3}, [%4];\n"
                 : "=r"(r[0]), "=r"(r[1]), "=r"(r[2]), "=r"(r[3]) : "r"(s));
}
__device__ __forceinline__ void mma16816(float* d, const uint32_t* a, const uint32_t* b) {
    asm volatile("mma.sync.aligned.m16n8k16.row.col.f32.f16.f16.f32 "
                 "{%0,%1,%2,%3}, {%4,%5,%6,%7}, {%8,%9}, {%0,%1,%2,%3};\n"
                 : "+f"(d[0]), "+f"(d[1]), "+f"(d[2]), "+f"(d[3])
                 : "r"(a[0]), "r"(a[1]), "r"(a[2]), "r"(a[3]), "r"(b[0]), "r"(b[1]));
}

__global__ __launch_bounds__(256, 1) void k_gemm(const float* __restrict__ bias,
                                                 float* __restrict__ out) {
    extern __shared__ char smem[];
    uint32_t sb;
    asm("{ .reg .u64 t; cvta.to.shared.u64 t, %1; cvt.u32.u64 %0, t; }"
        : "=r"(sb) : "l"((void*)smem));

    const int tid  = threadIdx.x;
    const int lane = tid & 31;
    const int warp = tid >> 5;
    const int warpM = warp >> 2;   // 0..1 -> 64-row slab
    const int warpN = warp & 3;    // 0..3 -> 64-col slab
    const int bm = blockIdx.y * BM;
    const int bn = blockIdx.x * BN;

    const __half* Ag = g_Xh;  // [m][k]
    const __half* Bg = g_Mt;  // [n][k]

    float acc[4][8][4];
#pragma unroll
    for (int i = 0; i < 4; i++)
#pragma unroll
        for (int j = 0; j < 8; j++)
#pragma unroll
            for (int k = 0; k < 4; k++) acc[i][j][k] = 0.f;

    // Pre-swizzled base offsets (base bits 5-6 are zero before swizzle, so the
    // per-k-slice ks*32 is applied later with XOR, never ADD).
    uint32_t aSw[4];
#pragma unroll
    for (int mi = 0; mi < 4; ++mi) {
        uint32_t off = (uint32_t)(warpM * 64 + mi * 16 + (lane & 15)) * 128
                     + (uint32_t)(lane >> 4) * 16;
        aSw[mi] = sw128(off);
    }
    uint32_t bSw[4];
#pragma unroll
    for (int p = 0; p < 4; ++p) {
        uint32_t row = (uint32_t)(warpN * 64 + p * 16 + ((lane & 16) >> 1) + (lane & 7));
        uint32_t off = row * 128 + (uint32_t)(lane & 8) * 2;
        bSw[p] = sw128(off);
    }

    // stage loader: 3072 x 16B chunks (1024 A + 2048 B), 12 per thread
    auto load_stage = [&](int s, int kt) {
        const int kk = kt * BK;
        const uint32_t base = sb + (uint32_t)s * STAGE_BYTES;
#pragma unroll
        for (int i = 0; i < 12; ++i) {
            int cid = tid + i * 256;
            if (cid < 1024) {                       // A: 128 rows x 8 chunks
                int r = cid >> 3, c = cid & 7;
                cp_async16(base + sw128((uint32_t)(r * 128 + c * 16)),
                           Ag + (size_t)(bm + r) * NF + kk + c * 8);
            } else {                                // B: 256 rows x 8 chunks
                int cid2 = cid - 1024;
                int r = cid2 >> 3, c = cid2 & 7;
                cp_async16(base + A_BYTES + sw128((uint32_t)(r * 128 + c * 16)),
                           Bg + (size_t)(bn + r) * NF + kk + c * 8);
            }
        }
        cp_commit();
    };

    load_stage(0, 0);
    load_stage(1, 1);
    load_stage(2, 2);

    for (int kt = 0; kt < KT; ++kt) {
        asm volatile("cp.async.wait_group 2;\n" ::: "memory");
        __syncthreads();       // stage kt landed; compute of kt-1 done before refill
        if (kt + 3 < KT) load_stage((kt + 3) & 3, kt + 3);
        else cp_commit();      // keep group count invariant

        const uint32_t stA = sb + (uint32_t)(kt & 3) * STAGE_BYTES;
        const uint32_t stB = stA + A_BYTES;
#pragma unroll
        for (int ks = 0; ks < 4; ++ks) {
            const uint32_t kx = (uint32_t)ks << 5;   // XOR into swizzled offset
            uint32_t af[4][4];
#pragma unroll
            for (int mi = 0; mi < 4; ++mi)
                ldmatrix_x4(af[mi], stA + (aSw[mi] ^ kx));
            uint32_t bf[4][4];
#pragma unroll
            for (int p = 0; p < 4; ++p)
                ldmatrix_x4(bf[p], stB + (bSw[p] ^ kx));
#pragma unroll
            for (int mi = 0; mi < 4; ++mi)
#pragma unroll
                for (int ni = 0; ni < 8; ++ni)
                    mma16816(acc[mi][ni], af[mi], &bf[ni >> 1][(ni & 1) * 2]);
        }
    }

    // epilogue: relu(acc + bias), fp32 out
#pragma unroll
    for (int mi = 0; mi < 4; ++mi) {
#pragma unroll
        for (int ni = 0; ni < 8; ++ni) {
            int row = bm + warpM * 64 + mi * 16 + (lane >> 2);
            int col = bn + warpN * 64 + ni * 8 + (lane & 3) * 2;
            float b0 = __ldg(bias + col), b1 = __ldg(bias + col + 1);
            float2 v0, v1;
            v0.x = fmaxf(acc[mi][ni][0] + b0, 0.f);
            v0.y = fmaxf(acc[mi][ni][1] + b1, 0.f);
            v1.x = fmaxf(acc[mi][ni][2] + b0, 0.f);
            v1.y = fmaxf(acc[mi][ni][3] + b1, 0.f);
            *(float2*)(out + (size_t)row * NF + col) = v0;
            *(float2*)(out + (size_t)(row + 8) * NF + col) = v1;
        }
    }
}

// ---------------------------------------------------------------------------

extern "C" void kernel_launch(void* const* d_in, const int* in_sizes, int n_in,
                              void* d_out, int out_size) {
    const float* x  = (const float*)d_in[0];
    const float* c0 = (const float*)d_in[1];
    const float* c1 = (const float*)d_in[2];
    const float* c2 = (const float*)d_in[3];
    const float* c3 = (const float*)d_in[4];
    const float* bv = (const float*)d_in[5];
    float* out = (float*)d_out;

    static bool attr_done = false;
    if (!attr_done) {
        cudaFuncSetAttribute(k_gemm, cudaFuncAttributeMaxDynamicSharedMemorySize,
                             SMEM_TOTAL);
        attr_done = true;
    }

    k_build_T2<<<256, 256>>>(c0, c1);
    k_build_T3<<<16384, 256>>>(c2);
    k_build_M<<<65536, 256>>>(c3);
    k_conv_x<<<16384, 256>>>((const float4*)x);

    dim3 grid(NF / BN, NF / BM);  // (16, 32)
    k_gemm<<<grid, 256, SMEM_TOTAL>>>(bv, out);
}